// round 3
// baseline (speedup 1.0000x reference)
#include <cuda_runtime.h>
#include <cuda_bf16.h>
#include <cstdint>

// ============================================================================
// SelfCorrelationStack: out = lam * x * (relu(x@W1+b1)@W2 + b2) + x
// S=8, rows/stack = 65536, D=H=64.  Target: plain sm_100 (NO tcgen05).
// Scheme: warp-level mma.sync bf16, 3-term hi/lo compensated fp32 emulation:
//   x@W ~= x_hi@W_hi + x_hi@W_lo + x_lo@W_hi      (error ~2^-16)
// Each warp owns 32 rows; h and x stay entirely in registers because the
// m16n8 C-fragment layout coincides with the m16n8k16 A-fragment layout.
// ============================================================================

static constexpr int NUM_CTAS  = 1024;   // 512 rows per CTA, 128 CTAs/stack
static constexpr int NS        = 2;      // strips (of 32 rows) per warp

// Weight image: per stack, 4 matrices [W1hi, W1lo, W2hi, W2lo],
// each stored as B[n][k] (n-major), 64 rows x 72 bf16 (144B stride, pad 8).
static constexpr int MAT_ELEMS   = 64 * 72;        // 4608
static constexpr int STACK_ELEMS = 4 * MAT_ELEMS;  // 18432
__device__ __align__(16) uint16_t g_wimg[8 * STACK_ELEMS];

// ---------------------------------------------------------------------------
// helpers
// ---------------------------------------------------------------------------
static __device__ __forceinline__ uint32_t smem_u32(const void* p) {
    uint32_t a;
    asm("{ .reg .u64 t; cvta.to.shared.u64 t, %1; cvt.u32.u64 %0, t; }"
        : "=r"(a) : "l"(p));
    return a;
}

// packed bf16x2: low half = hi16(a), high half = hi16(b)  (truncation split)
static __device__ __forceinline__ uint32_t prmt_hi(float a, float b) {
    uint32_t r;
    asm("prmt.b32 %0, %1, %2, 0x7632;"
        : "=r"(r) : "r"(__float_as_uint(a)), "r"(__float_as_uint(b)));
    return r;
}
// residual (a - trunc16(a)) rounded to bf16, packed; low half = elem a
static __device__ __forceinline__ uint32_t pack_lo(float a, float b) {
    float fa = __uint_as_float(__float_as_uint(a) & 0xFFFF0000u);
    float fb = __uint_as_float(__float_as_uint(b) & 0xFFFF0000u);
    float la = a - fa;
    float lb = b - fb;
    uint32_t r;
    asm("cvt.rn.bf16x2.f32 %0, %1, %2;" : "=r"(r) : "f"(lb), "f"(la));
    return r;
}

static __device__ __forceinline__ void mma16816(float* d, const uint32_t* a,
                                                const uint32_t* b) {
    asm volatile(
        "mma.sync.aligned.m16n8k16.row.col.f32.bf16.bf16.f32 "
        "{%0,%1,%2,%3}, {%4,%5,%6,%7}, {%8,%9}, {%0,%1,%2,%3};"
        : "+f"(d[0]), "+f"(d[1]), "+f"(d[2]), "+f"(d[3])
        : "r"(a[0]), "r"(a[1]), "r"(a[2]), "r"(a[3]), "r"(b[0]), "r"(b[1]));
}

static __device__ __forceinline__ void ldsm4(uint32_t* r, uint32_t addr) {
    asm volatile(
        "ldmatrix.sync.aligned.m8n8.x4.shared.b16 {%0,%1,%2,%3}, [%4];"
        : "=r"(r[0]), "=r"(r[1]), "=r"(r[2]), "=r"(r[3]) : "r"(addr));
}

// ---------------------------------------------------------------------------
// Prep: transpose + truncation hi/lo split weights into padded n-major image.
// B[n][k] = W[s, k, n].  mat 0/1 = W1 hi/lo, mat 2/3 = W2 hi/lo.
// ---------------------------------------------------------------------------
__global__ void scs_prep(const float* __restrict__ W1,
                         const float* __restrict__ W2) {
    int s = blockIdx.x;
    uint16_t* img = g_wimg + (size_t)s * STACK_ELEMS;
    for (int e = threadIdx.x; e < 8192; e += blockDim.x) {
        int m2 = e >> 12;            // 0: W1, 1: W2
        int i = e & 4095;
        int n = i >> 6;
        int k = i & 63;
        const float* W = m2 ? W2 : W1;
        float v = W[s * 4096 + k * 64 + n];
        uint32_t hv = __float_as_uint(v) & 0xFFFF0000u;
        float lo = v - __uint_as_float(hv);
        img[(m2 * 2 + 0) * MAT_ELEMS + n * 72 + k] = (uint16_t)(hv >> 16);
        img[(m2 * 2 + 1) * MAT_ELEMS + n * 72 + k] =
            __bfloat16_as_ushort(__float2bfloat16(lo));
    }
}

// ---------------------------------------------------------------------------
// GEMM layer: acc[2][8][4] += Ahi@Whi + Alo@Whi + Ahi@Wlo
// W base addresses are smem (u32). laneRow = per-lane ldmatrix row offset.
// ---------------------------------------------------------------------------
static __device__ __forceinline__ void gemm_layer(
    float acc[2][8][4],
    const uint32_t Ahi[2][4][4], const uint32_t Alo[2][4][4],
    uint32_t whi, uint32_t wlo, uint32_t laneRow) {
    // pass 1: Whi, used by both Ahi and Alo
    #pragma unroll
    for (int m = 0; m < 4; m++) {
        uint32_t b[8][2];
        #pragma unroll
        for (int jp = 0; jp < 4; jp++) {
            uint32_t rr[4];
            ldsm4(rr, whi + jp * 2304 + m * 32 + laneRow);
            b[2 * jp][0] = rr[0]; b[2 * jp][1] = rr[1];
            b[2 * jp + 1][0] = rr[2]; b[2 * jp + 1][1] = rr[3];
        }
        #pragma unroll
        for (int mt = 0; mt < 2; mt++)
            #pragma unroll
            for (int j = 0; j < 8; j++) mma16816(acc[mt][j], Ahi[mt][m], b[j]);
        #pragma unroll
        for (int mt = 0; mt < 2; mt++)
            #pragma unroll
            for (int j = 0; j < 8; j++) mma16816(acc[mt][j], Alo[mt][m], b[j]);
    }
    // pass 2: Wlo, with Ahi only
    #pragma unroll
    for (int m = 0; m < 4; m++) {
        uint32_t b[8][2];
        #pragma unroll
        for (int jp = 0; jp < 4; jp++) {
            uint32_t rr[4];
            ldsm4(rr, wlo + jp * 2304 + m * 32 + laneRow);
            b[2 * jp][0] = rr[0]; b[2 * jp][1] = rr[1];
            b[2 * jp + 1][0] = rr[2]; b[2 * jp + 1][1] = rr[3];
        }
        #pragma unroll
        for (int mt = 0; mt < 2; mt++)
            #pragma unroll
            for (int j = 0; j < 8; j++) mma16816(acc[mt][j], Ahi[mt][m], b[j]);
    }
}

// ---------------------------------------------------------------------------
// Main kernel: 256 threads (8 warps), 512 rows per CTA (2 strips of 32/warp).
// ---------------------------------------------------------------------------
__global__ void __launch_bounds__(256, 1)
scs_main(const float* __restrict__ x,
         const float* __restrict__ b1g,
         const float* __restrict__ b2g,
         const float* __restrict__ lamg,
         float* __restrict__ out) {
    __shared__ __align__(16) uint16_t sW[STACK_ELEMS];
    __shared__ float sB1[64];
    __shared__ float sB2[64];
    __shared__ float sLam;

    const int cta = blockIdx.x;
    const int s = cta >> 7;                 // 128 CTAs per stack
    const int tid = threadIdx.x;
    const int w = tid >> 5;
    const int l = tid & 31;
    const int g = l >> 2;
    const int t = l & 3;

    // load weight image + biases
    {
        const uint4* src = reinterpret_cast<const uint4*>(g_wimg + (size_t)s * STACK_ELEMS);
        uint4* dst = reinterpret_cast<uint4*>(sW);
        #pragma unroll
        for (int i = 0; i < 9; i++) dst[tid + i * 256] = src[tid + i * 256];
    }
    if (tid < 64)           sB1[tid] = b1g[s * 64 + tid];
    else if (tid < 128)     sB2[tid - 64] = b2g[s * 64 + (tid - 64)];
    else if (tid == 128)    sLam = lamg[s];
    __syncthreads();

    const float lam = sLam;
    const uint32_t swb = smem_u32(sW);
    const uint32_t w1hi = swb;
    const uint32_t w1lo = swb + 2 * MAT_ELEMS;
    const uint32_t w2hi = swb + 4 * MAT_ELEMS;
    const uint32_t w2lo = swb + 6 * MAT_ELEMS;
    // ldmatrix per-lane row offset: L = lane>>3 selects matrix, r = lane&7 row
    const int L = l >> 3, r = l & 7;
    const uint32_t laneRow = (uint32_t)((8 * (L >> 1) + r) * 144 + 16 * (L & 1));

    #pragma unroll 1
    for (int ns = 0; ns < NS; ns++) {
        const int rowBase = cta * 512 + w * (NS * 32) + ns * 32;

        // ---- load x, split into A fragments (hi/lo) ----
        uint32_t xhi[2][4][4], xlo[2][4][4];
        #pragma unroll
        for (int mt = 0; mt < 2; mt++) {
            const float2* p0 = reinterpret_cast<const float2*>(
                x + (size_t)(rowBase + mt * 16 + g) * 64);
            const float2* p1 = reinterpret_cast<const float2*>(
                x + (size_t)(rowBase + mt * 16 + g + 8) * 64);
            #pragma unroll
            for (int m = 0; m < 4; m++) {
                float2 v00 = p0[8 * m + t];        // row g,   k 16m+2t
                float2 v10 = p1[8 * m + t];        // row g+8, k 16m+2t
                float2 v01 = p0[8 * m + 4 + t];    // row g,   k 16m+8+2t
                float2 v11 = p1[8 * m + 4 + t];    // row g+8, k 16m+8+2t
                xhi[mt][m][0] = prmt_hi(v00.x, v00.y);
                xlo[mt][m][0] = pack_lo(v00.x, v00.y);
                xhi[mt][m][1] = prmt_hi(v10.x, v10.y);
                xlo[mt][m][1] = pack_lo(v10.x, v10.y);
                xhi[mt][m][2] = prmt_hi(v01.x, v01.y);
                xlo[mt][m][2] = pack_lo(v01.x, v01.y);
                xhi[mt][m][3] = prmt_hi(v11.x, v11.y);
                xlo[mt][m][3] = pack_lo(v11.x, v11.y);
            }
        }

        // ---- layer 1: h = relu(x@W1 + b1) ----
        float acc[2][8][4];
        #pragma unroll
        for (int mt = 0; mt < 2; mt++)
            #pragma unroll
            for (int j = 0; j < 8; j++)
                #pragma unroll
                for (int c = 0; c < 4; c++) acc[mt][j][c] = 0.0f;

        gemm_layer(acc, xhi, xlo, w1hi, w1lo, laneRow);

        // epilogue 1: bias + relu, split to A-fragments for layer 2
        uint32_t hhi[2][4][4], hlo[2][4][4];
        #pragma unroll
        for (int mt = 0; mt < 2; mt++) {
            #pragma unroll
            for (int j = 0; j < 8; j++) {
                float2 bb = reinterpret_cast<const float2*>(sB1)[4 * j + t];
                float h0 = fmaxf(acc[mt][j][0] + bb.x, 0.0f);
                float h1 = fmaxf(acc[mt][j][1] + bb.y, 0.0f);
                float h2 = fmaxf(acc[mt][j][2] + bb.x, 0.0f);
                float h3 = fmaxf(acc[mt][j][3] + bb.y, 0.0f);
                const int m = j >> 1, p = (j & 1) * 2;
                hhi[mt][m][p]     = prmt_hi(h0, h1);
                hlo[mt][m][p]     = pack_lo(h0, h1);
                hhi[mt][m][p + 1] = prmt_hi(h2, h3);
                hlo[mt][m][p + 1] = pack_lo(h2, h3);
            }
        }

        // ---- layer 2: w = h@W2 + b2 ----
        #pragma unroll
        for (int mt = 0; mt < 2; mt++)
            #pragma unroll
            for (int j = 0; j < 8; j++)
                #pragma unroll
                for (int c = 0; c < 4; c++) acc[mt][j][c] = 0.0f;

        gemm_layer(acc, hhi, hlo, w2hi, w2lo, laneRow);

        // epilogue 2: out = lam*x*w + x   (x reconstructed = hi + lo, ~2^-17)
        #pragma unroll
        for (int mt = 0; mt < 2; mt++) {
            float2* o0 = reinterpret_cast<float2*>(
                out + (size_t)(rowBase + mt * 16 + g) * 64);
            float2* o1 = reinterpret_cast<float2*>(
                out + (size_t)(rowBase + mt * 16 + g + 8) * 64);
            #pragma unroll
            for (int j = 0; j < 8; j++) {
                float2 bb = reinterpret_cast<const float2*>(sB2)[4 * j + t];
                float w0 = acc[mt][j][0] + bb.x;
                float w1 = acc[mt][j][1] + bb.y;
                float w2v = acc[mt][j][2] + bb.x;
                float w3 = acc[mt][j][3] + bb.y;
                const int m = j >> 1, p = (j & 1) * 2;
                uint32_t rh0 = xhi[mt][m][p],     rl0 = xlo[mt][m][p];
                uint32_t rh1 = xhi[mt][m][p + 1], rl1 = xlo[mt][m][p + 1];
                float x0 = __uint_as_float(rh0 << 16) + __uint_as_float(rl0 << 16);
                float x1 = __uint_as_float(rh0 & 0xFFFF0000u) +
                           __uint_as_float(rl0 & 0xFFFF0000u);
                float x2 = __uint_as_float(rh1 << 16) + __uint_as_float(rl1 << 16);
                float x3 = __uint_as_float(rh1 & 0xFFFF0000u) +
                           __uint_as_float(rl1 & 0xFFFF0000u);
                float2 s0, s1;
                s0.x = fmaf(x0, lam * w0, x0);
                s0.y = fmaf(x1, lam * w1, x1);
                s1.x = fmaf(x2, lam * w2v, x2);
                s1.y = fmaf(x3, lam * w3, x3);
                o0[4 * j + t] = s0;
                o1[4 * j + t] = s1;
            }
        }
    }
}

// ---------------------------------------------------------------------------
extern "C" void kernel_launch(void* const* d_in, const int* in_sizes, int n_in,
                              void* d_out, int out_size) {
    const float* x   = (const float*)d_in[0];
    const float* W1  = (const float*)d_in[1];
    const float* b1  = (const float*)d_in[2];
    const float* W2  = (const float*)d_in[3];
    const float* b2  = (const float*)d_in[4];
    const float* lam = (const float*)d_in[5];
    float* out = (float*)d_out;

    scs_prep<<<8, 256>>>(W1, W2);
    scs_main<<<NUM_CTAS, 256>>>(x, b1, b2, lam, out);
}